// round 15
// baseline (speedup 1.0000x reference)
#include <cuda_runtime.h>
#include <cuda_bf16.h>
#include <math.h>
#include <cstdint>

#define HQ_  32
#define HKV_ 8
#define D_   64
#define HID_ 2048
#define B_   2
#define T_   2048
#define M_   (B_*T_)          // 4096 rows (B*T)
#define NQKV_ 3072            // 2048 (Q) + 512 (K) + 512 (V)

typedef unsigned long long ull;

// ---------------- packed f32x2 (attention path, validated R4) --------------
#define FMA_F32X2(d, a, b, c) \
    asm("fma.rn.f32x2 %0, %1, %2, %3;" : "=l"(d) : "l"(a), "l"(b), "l"(c))
#define MUL_F32X2(d, a, b) \
    asm("mul.rn.f32x2 %0, %1, %2;" : "=l"(d) : "l"(a), "l"(b))
#define PACK_F32X2(d, lo, hi) \
    asm("mov.b64 %0, {%1, %2};" : "=l"(d) \
        : "r"(__float_as_uint(lo)), "r"(__float_as_uint(hi)))
#define UNPACK_F32X2(lo, hi, s) do {                                   \
    unsigned _u0, _u1;                                                 \
    asm("mov.b64 {%0, %1}, %2;" : "=r"(_u0), "=r"(_u1) : "l"(s));      \
    (lo) = __uint_as_float(_u0); (hi) = __uint_as_float(_u1);          \
} while (0)

// ---------------- plain-target async copy (sm_80+ base features) -----------
#define CP_ASYNC16(saddr, gptr) \
    asm volatile("cp.async.cg.shared.global [%0], [%1], 16;" \
        :: "r"(saddr), "l"(gptr))
#define CP_COMMIT() asm volatile("cp.async.commit_group;" ::: "memory")
#define CP_WAIT1()  asm volatile("cp.async.wait_group 1;" ::: "memory")
#define CP_WAIT0()  asm volatile("cp.async.wait_group 0;" ::: "memory")

__device__ __forceinline__ uint32_t smem_to_u32(const void* p) {
    uint32_t a;
    asm("{ .reg .u64 t; cvta.to.shared.u64 t, %1; cvt.u32.u64 %0, t; }"
        : "=r"(a) : "l"(p));
    return a;
}

// mma.sync m16n8k16 bf16 -> f32 (plain-target tensor core path)
__device__ __forceinline__ void mma16816(float* c, const uint32_t* a, const uint32_t* b)
{
    asm volatile(
        "mma.sync.aligned.m16n8k16.row.col.f32.bf16.bf16.f32 "
        "{%0,%1,%2,%3}, {%4,%5,%6,%7}, {%8,%9}, {%0,%1,%2,%3};"
        : "+f"(c[0]), "+f"(c[1]), "+f"(c[2]), "+f"(c[3])
        : "r"(a[0]), "r"(a[1]), "r"(a[2]), "r"(a[3]), "r"(b[0]), "r"(b[1]));
}

// Fast exp2 on the fma/alu pipes (replaces MUFU __expf — the attention
// bottleneck: 150M exps at MUFU 74/cyc/chip ≈ 1.1ms; this is ~12 fma/alu ops).
// Degree-6 Taylor of 2^f on [0,1): max rel err ~2e-5. t<=0 expected; t very
// negative (masked -1e30) clamps to 2^-126 ~= 0.
__device__ __forceinline__ float exp2_fast(float t)
{
    t = fmaxf(t, -126.0f);
    float fi = floorf(t);
    float f = t - fi;
    float p = 1.5403530393381609e-4f;               // ln2^6/720
    p = fmaf(p, f, 1.3333558146428443e-3f);         // ln2^5/120
    p = fmaf(p, f, 9.6181291076284772e-3f);         // ln2^4/24
    p = fmaf(p, f, 5.5504108664821580e-2f);         // ln2^3/6
    p = fmaf(p, f, 2.4022650695910071e-1f);         // ln2^2/2
    p = fmaf(p, f, 6.9314718055994531e-1f);         // ln2
    p = fmaf(p, f, 1.0f);
    int ei = (int)fi;
    float sc = __int_as_float((ei + 127) << 23);
    return p * sc;
}

// ---------------- scratch (device globals; no runtime allocation) ----------
__device__ float g_QKV[(size_t)M_ * NQKV_];
__device__ float g_Q[(size_t)B_ * HQ_ * T_ * D_];
__device__ float g_K[(size_t)B_ * HKV_ * T_ * D_];
__device__ float g_V[(size_t)B_ * HKV_ * T_ * D_];
__device__ float g_attn[(size_t)M_ * HQ_ * D_];
// bf16 hi/lo split operands
__device__ __nv_bfloat16 g_hid_h[(size_t)M_ * HID_],  g_hid_l[(size_t)M_ * HID_];
__device__ __nv_bfloat16 g_w_h[(size_t)NQKV_ * HID_], g_w_l[(size_t)NQKV_ * HID_];
__device__ __nv_bfloat16 g_ow_h[(size_t)HID_ * HQ_ * D_], g_ow_l[(size_t)HID_ * HQ_ * D_];
__device__ __nv_bfloat16 g_at_h[(size_t)M_ * HQ_ * D_],  g_at_l[(size_t)M_ * HQ_ * D_];

// ---------------------------------------------------------------------------
// fp32 -> (bf16 hi, bf16 lo) split conversion, 4 elements/thread.
// ---------------------------------------------------------------------------
__global__ __launch_bounds__(256) void cvt_hilo(
    const float* __restrict__ x, __nv_bfloat16* __restrict__ hi,
    __nv_bfloat16* __restrict__ lo, int n4)
{
    int i = blockIdx.x * blockDim.x + threadIdx.x;
    if (i >= n4) return;
    float4 v = ((const float4*)x)[i];
    __nv_bfloat16 h0 = __float2bfloat16(v.x), h1 = __float2bfloat16(v.y);
    __nv_bfloat16 h2 = __float2bfloat16(v.z), h3 = __float2bfloat16(v.w);
    __nv_bfloat16 l0 = __float2bfloat16(v.x - __bfloat162float(h0));
    __nv_bfloat16 l1 = __float2bfloat16(v.y - __bfloat162float(h1));
    __nv_bfloat16 l2 = __float2bfloat16(v.z - __bfloat162float(h2));
    __nv_bfloat16 l3 = __float2bfloat16(v.w - __bfloat162float(h3));
    ((__nv_bfloat162*)hi)[2*i]   = __nv_bfloat162(h0, h1);
    ((__nv_bfloat162*)hi)[2*i+1] = __nv_bfloat162(h2, h3);
    ((__nv_bfloat162*)lo)[2*i]   = __nv_bfloat162(l0, l1);
    ((__nv_bfloat162*)lo)[2*i+1] = __nv_bfloat162(l2, l3);
}

// ---------------------------------------------------------------------------
// Split-bf16 NT GEMM on mma.sync tensor cores (validated R12).
// ---------------------------------------------------------------------------
#define ROWB 80                        // padded row stride in bytes
#define ARRB (128 * ROWB)              // one operand tile: 10240 B
#define STAGEB (4 * ARRB)              // 4 operand tiles per stage: 40960 B
#define MG_SMEM (2 * STAGEB)           // double buffered: 81920 B

__device__ __forceinline__ void mma_gemm_tile(
    const __nv_bfloat16* __restrict__ Ah, const __nv_bfloat16* __restrict__ Al,
    const __nv_bfloat16* __restrict__ Bh, const __nv_bfloat16* __restrict__ Bl,
    float* __restrict__ C, int K, int ldc, int bm, int bnW, int bnC)
{
    extern __shared__ char dsm[];
    const uint32_t sbase = smem_to_u32(dsm);
    const int tid = threadIdx.x;
    const int wid = tid >> 5, lane = tid & 31;
    const int wm = wid >> 2, wn = wid & 3;     // warp 2x4 grid
    const int g = lane >> 2, tig = lane & 3;   // groupID, thread-in-group

    const __nv_bfloat16* gsrc[8];
    uint32_t sdst[8];
    #pragma unroll
    for (int i = 0; i < 8; i++) {
        const int id = tid + i * 256;
        const int arr = id >> 9, rem = id & 511;
        const int row = rem >> 2, seg = rem & 3;
        const __nv_bfloat16* base;
        if      (arr == 0) base = Ah + (size_t)(bm  + row) * K;
        else if (arr == 1) base = Al + (size_t)(bm  + row) * K;
        else if (arr == 2) base = Bh + (size_t)(bnW + row) * K;
        else               base = Bl + (size_t)(bnW + row) * K;
        gsrc[i] = base + seg * 8;
        sdst[i] = sbase + arr * ARRB + row * ROWB + seg * 16;
    }

    float acc[4][4][4];
    #pragma unroll
    for (int mt = 0; mt < 4; mt++)
        #pragma unroll
        for (int nt = 0; nt < 4; nt++)
            #pragma unroll
            for (int r = 0; r < 4; r++) acc[mt][nt][r] = 0.f;

    const int S = K >> 5;   // 32-wide stages
    #pragma unroll
    for (int i = 0; i < 8; i++) CP_ASYNC16(sdst[i], gsrc[i]);
    CP_COMMIT();

    for (int s = 0; s < S; s++) {
        if (s + 1 < S) {
            const uint32_t boff = ((s + 1) & 1) * STAGEB;
            const int k0 = (s + 1) << 5;
            #pragma unroll
            for (int i = 0; i < 8; i++) CP_ASYNC16(sdst[i] + boff, gsrc[i] + k0);
            CP_COMMIT();
            CP_WAIT1();
        } else {
            CP_WAIT0();
        }
        __syncthreads();

        const char* sb = dsm + (s & 1) * STAGEB;
        const char* AHs = sb;
        const char* ALs = sb + ARRB;
        const char* BHs = sb + 2 * ARRB;
        const char* BLs = sb + 3 * ARRB;

        #pragma unroll
        for (int kk = 0; kk < 2; kk++) {
            const int wb = kk * 8;
            uint32_t ah[4][4], al[4][4], bh[4][2], bl[4][2];
            #pragma unroll
            for (int mt = 0; mt < 4; mt++) {
                const int r0 = wm * 64 + mt * 16 + g;
                const uint32_t o00 = r0 * ROWB + (wb + tig) * 4;
                const uint32_t o10 = (r0 + 8) * ROWB + (wb + tig) * 4;
                ah[mt][0] = *(const uint32_t*)(AHs + o00);
                ah[mt][1] = *(const uint32_t*)(AHs + o10);
                ah[mt][2] = *(const uint32_t*)(AHs + o00 + 16);
                ah[mt][3] = *(const uint32_t*)(AHs + o10 + 16);
                al[mt][0] = *(const uint32_t*)(ALs + o00);
                al[mt][1] = *(const uint32_t*)(ALs + o10);
                al[mt][2] = *(const uint32_t*)(ALs + o00 + 16);
                al[mt][3] = *(const uint32_t*)(ALs + o10 + 16);
            }
            #pragma unroll
            for (int nt = 0; nt < 4; nt++) {
                const int n = wn * 32 + nt * 8 + g;
                const uint32_t o = n * ROWB + (wb + tig) * 4;
                bh[nt][0] = *(const uint32_t*)(BHs + o);
                bh[nt][1] = *(const uint32_t*)(BHs + o + 16);
                bl[nt][0] = *(const uint32_t*)(BLs + o);
                bl[nt][1] = *(const uint32_t*)(BLs + o + 16);
            }
            #pragma unroll
            for (int mt = 0; mt < 4; mt++)
                #pragma unroll
                for (int nt = 0; nt < 4; nt++) {
                    mma16816(acc[mt][nt], ah[mt], bh[nt]);
                    mma16816(acc[mt][nt], ah[mt], bl[nt]);
                    mma16816(acc[mt][nt], al[mt], bh[nt]);
                }
        }
        __syncthreads();
    }

    #pragma unroll
    for (int mt = 0; mt < 4; mt++) {
        const int r0 = bm + wm * 64 + mt * 16 + g;
        #pragma unroll
        for (int nt = 0; nt < 4; nt++) {
            float* cp = C + (size_t)r0 * ldc + bnC + wn * 32 + nt * 8 + tig * 2;
            *(float2*)cp = make_float2(acc[mt][nt][0], acc[mt][nt][1]);
            *(float2*)(cp + (size_t)8 * ldc) = make_float2(acc[mt][nt][2], acc[mt][nt][3]);
        }
    }
}

__global__ __launch_bounds__(256) void qkv_gemm(
    const __nv_bfloat16* __restrict__ hidh, const __nv_bfloat16* __restrict__ hidl,
    const __nv_bfloat16* __restrict__ wh,   const __nv_bfloat16* __restrict__ wl,
    float* __restrict__ C)
{
    const int bn = blockIdx.x * 128;
    mma_gemm_tile(hidh, hidl, wh, wl, C, HID_, NQKV_, blockIdx.y * 128, bn, bn);
}

__global__ __launch_bounds__(256) void o_gemm(
    const __nv_bfloat16* __restrict__ ah, const __nv_bfloat16* __restrict__ al,
    const __nv_bfloat16* __restrict__ wh, const __nv_bfloat16* __restrict__ wl,
    float* __restrict__ C)
{
    mma_gemm_tile(ah, al, wh, wl, C, HQ_ * D_, HID_,
                  blockIdx.y * 128, blockIdx.x * 128, blockIdx.x * 128);
}

// ---------------------------------------------------------------------------
// Bias add + RoPE + layout transform (unchanged, validated).
// ---------------------------------------------------------------------------
__global__ __launch_bounds__(128) void rope_reshape(
    const float* __restrict__ qkv,
    const float* __restrict__ qb, const float* __restrict__ kb,
    const float* __restrict__ vb,
    float* __restrict__ Q, float* __restrict__ K, float* __restrict__ V)
{
    const int bt = blockIdx.x;
    const int b = bt / T_, t = bt % T_;
    const float* row = qkv + (size_t)bt * NQKV_;
    const float pos = (float)t;
    const float LOG_TH_OVER_HALF = 9.210340371976184f / 32.0f;

    for (int it = threadIdx.x; it < HQ_*32; it += blockDim.x) {
        int h = it >> 5, j = it & 31;
        float invf = expf(-(float)j * LOG_TH_OVER_HALF);
        float sn, cs; sincosf(pos * invf, &sn, &cs);
        float x1 = row[h*64 + j]      + qb[h*64 + j];
        float x2 = row[h*64 + j + 32] + qb[h*64 + j + 32];
        float* o = Q + (((size_t)b*HQ_ + h)*T_ + t)*64;
        o[j]      = x1*cs - x2*sn;
        o[j + 32] = x2*cs + x1*sn;
    }
    for (int it = threadIdx.x; it < HKV_*32; it += blockDim.x) {
        int h = it >> 5, j = it & 31;
        float invf = expf(-(float)j * LOG_TH_OVER_HALF);
        float sn, cs; sincosf(pos * invf, &sn, &cs);
        float x1 = row[2048 + h*64 + j]      + kb[h*64 + j];
        float x2 = row[2048 + h*64 + j + 32] + kb[h*64 + j + 32];
        float* o = K + (((size_t)b*HKV_ + h)*T_ + t)*64;
        o[j]      = x1*cs - x2*sn;
        o[j + 32] = x2*cs + x1*sn;
    }
    for (int it = threadIdx.x; it < HKV_*64; it += blockDim.x) {
        V[(((size_t)b*HKV_ + (it >> 6))*T_ + t)*64 + (it & 63)] =
            row[2560 + it] + vb[it];
    }
}

// ---------------------------------------------------------------------------
// Flash-style causal GQA attention in packed f32x2. Scores kept in log2
// domain (log2(e)/sqrt(D) folded into q); all exps are fma-pipe exp2_fast,
// eliminating the MUFU bottleneck (~150M MUFU ops -> ~0).
// ---------------------------------------------------------------------------
__global__ __launch_bounds__(128) void attn_kernel(
    const float* __restrict__ Q, const float* __restrict__ K,
    const float* __restrict__ V, float* __restrict__ O)
{
    const int qt = (gridDim.x - 1) - blockIdx.x;
    const int bh = blockIdx.y;
    const int b = bh / HQ_, h = bh % HQ_;
    const int kvh = h / (HQ_ / HKV_);
    const float* Qp = Q + (((size_t)b*HQ_  + h  )*T_) * D_;
    const float* Kp = K + (((size_t)b*HKV_ + kvh)*T_) * D_;
    const float* Vp = V + (((size_t)b*HKV_ + kvh)*T_) * D_;
    const int i = qt*128 + threadIdx.x;

    // fold (1/sqrt(D)) * log2(e) into q: scores land in log2 domain
    const float QSCALE = 0.125f * 1.4426950408889634f;
    ull q2[32];
    {
        const float4* qr = (const float4*)(Qp + (size_t)i * D_);
        #pragma unroll
        for (int d4 = 0; d4 < 16; d4++) {
            float4 v = qr[d4];
            PACK_F32X2(q2[2*d4],   v.x*QSCALE, v.y*QSCALE);
            PACK_F32X2(q2[2*d4+1], v.z*QSCALE, v.w*QSCALE);
        }
    }
    ull acc2[32];
    #pragma unroll
    for (int d = 0; d < 32; d++) acc2[d] = 0ull;
    float m = -1e30f, l = 0.f;

    __shared__ float Ks[64][64];
    __shared__ float Vs[64][64];

    const int nkt = 2*qt + 2;
    for (int kt = 0; kt < nkt; kt++) {
        __syncthreads();
        const float4* Ksrc = (const float4*)(Kp + (size_t)kt*64*D_);
        const float4* Vsrc = (const float4*)(Vp + (size_t)kt*64*D_);
        for (int u = threadIdx.x; u < 1024; u += 128) {
            ((float4*)Ks)[u] = Ksrc[u];
            ((float4*)Vs)[u] = Vsrc[u];
        }
        __syncthreads();

        const int base = kt*64;
        const bool diag = (base + 63 > i);
        #pragma unroll 1
        for (int j0 = 0; j0 < 64; j0 += 8) {
            float s[8];
            #pragma unroll
            for (int c = 0; c < 8; c++) {
                const ulonglong2* kr = (const ulonglong2*)Ks[j0 + c];
                ull d2a = 0ull, d2b = 0ull;
                #pragma unroll
                for (int d4 = 0; d4 < 8; d4++) {
                    ulonglong2 k0 = kr[d4];
                    ulonglong2 k1 = kr[d4+8];
                    FMA_F32X2(d2a, q2[2*d4],    k0.x, d2a);
                    FMA_F32X2(d2a, q2[2*d4+1],  k0.y, d2a);
                    FMA_F32X2(d2b, q2[16+2*d4], k1.x, d2b);
                    FMA_F32X2(d2b, q2[17+2*d4], k1.y, d2b);
                }
                float e0,e1,e2,e3;
                UNPACK_F32X2(e0, e1, d2a);
                UNPACK_F32X2(e2, e3, d2b);
                s[c] = (e0 + e1) + (e2 + e3);
            }
            if (diag) {
                #pragma unroll
                for (int c = 0; c < 8; c++)
                    if (base + j0 + c > i) s[c] = -1e30f;
            }
            float cm = s[0];
            #pragma unroll
            for (int c = 1; c < 8; c++) cm = fmaxf(cm, s[c]);
            float mn = fmaxf(m, cm);
            float sc = exp2_fast(m - mn);
            float p[8], ps = 0.f;
            #pragma unroll
            for (int c = 0; c < 8; c++) { p[c] = exp2_fast(s[c] - mn); ps += p[c]; }
            l = l*sc + ps;
            m = mn;
            ull sc2; PACK_F32X2(sc2, sc, sc);
            ull p2[8];
            #pragma unroll
            for (int c = 0; c < 8; c++) PACK_F32X2(p2[c], p[c], p[c]);
            #pragma unroll
            for (int d4 = 0; d4 < 16; d4++) {
                ull a0 = acc2[2*d4], a1 = acc2[2*d4+1];
                MUL_F32X2(a0, a0, sc2);
                MUL_F32X2(a1, a1, sc2);
                #pragma unroll
                for (int c = 0; c < 8; c++) {
                    ulonglong2 vv = ((const ulonglong2*)Vs[j0 + c])[d4];
                    FMA_F32X2(a0, p2[c], vv.x, a0);
                    FMA_F32X2(a1, p2[c], vv.y, a1);
                }
                acc2[2*d4] = a0; acc2[2*d4+1] = a1;
            }
        }
    }

    const float inv = 1.0f / l;
    float* Op = O + (((size_t)(b*T_ + i))*HQ_ + h) * D_;
    #pragma unroll
    for (int d4 = 0; d4 < 16; d4++) {
        float o0,o1,o2,o3;
        UNPACK_F32X2(o0, o1, acc2[2*d4]);
        UNPACK_F32X2(o2, o3, acc2[2*d4+1]);
        ((float4*)Op)[d4] = make_float4(o0*inv, o1*inv, o2*inv, o3*inv);
    }
}

// ---------------------------------------------------------------------------
extern "C" void kernel_launch(void* const* d_in, const int* in_sizes, int n_in,
                              void* d_out, int out_size)
{
    (void)in_sizes; (void)n_in; (void)out_size;
    const float* hidden = (const float*)d_in[0];
    const float* q_w = (const float*)d_in[3];
    const float* q_b = (const float*)d_in[4];
    const float* k_w = (const float*)d_in[5];
    const float* k_b = (const float*)d_in[6];
    const float* v_w = (const float*)d_in[7];
    const float* v_b = (const float*)d_in[8];
    const float* o_w = (const float*)d_in[9];
    float* out = (float*)d_out;

    float *qkv, *Qb, *Kb, *Vb, *attnb;
    cudaGetSymbolAddress((void**)&qkv,   g_QKV);
    cudaGetSymbolAddress((void**)&Qb,    g_Q);
    cudaGetSymbolAddress((void**)&Kb,    g_K);
    cudaGetSymbolAddress((void**)&Vb,    g_V);
    cudaGetSymbolAddress((void**)&attnb, g_attn);
    __nv_bfloat16 *hidh, *hidl, *wh, *wl, *owh, *owl, *ath, *atl;
    cudaGetSymbolAddress((void**)&hidh, g_hid_h);
    cudaGetSymbolAddress((void**)&hidl, g_hid_l);
    cudaGetSymbolAddress((void**)&wh,   g_w_h);
    cudaGetSymbolAddress((void**)&wl,   g_w_l);
    cudaGetSymbolAddress((void**)&owh,  g_ow_h);
    cudaGetSymbolAddress((void**)&owl,  g_ow_l);
    cudaGetSymbolAddress((void**)&ath,  g_at_h);
    cudaGetSymbolAddress((void**)&atl,  g_at_l);

    cudaFuncSetAttribute(qkv_gemm, cudaFuncAttributeMaxDynamicSharedMemorySize, MG_SMEM);
    cudaFuncSetAttribute(o_gemm,   cudaFuncAttributeMaxDynamicSharedMemorySize, MG_SMEM);

    // hi/lo split conversions
    {
        int n4;
        n4 = (M_*HID_)/4;       cvt_hilo<<<(n4+255)/256, 256>>>(hidden, hidh, hidl, n4);
        n4 = (2048*HID_)/4;     cvt_hilo<<<(n4+255)/256, 256>>>(q_w, wh, wl, n4);
        n4 = (512*HID_)/4;      cvt_hilo<<<(n4+255)/256, 256>>>(k_w, wh + (size_t)2048*HID_, wl + (size_t)2048*HID_, n4);
        n4 = (512*HID_)/4;      cvt_hilo<<<(n4+255)/256, 256>>>(v_w, wh + (size_t)2560*HID_, wl + (size_t)2560*HID_, n4);
        n4 = (HID_*HQ_*D_)/4;   cvt_hilo<<<(n4+255)/256, 256>>>(o_w, owh, owl, n4);
    }

    // QKV projection on tensor cores (bias deferred to rope_reshape)
    qkv_gemm<<<dim3(NQKV_/128, M_/128), 256, MG_SMEM>>>(hidh, hidl, wh, wl, qkv);

    // bias + RoPE + relayout
    rope_reshape<<<M_, 128>>>(qkv, q_b, k_b, v_b, Qb, Kb, Vb);

    // causal GQA attention
    attn_kernel<<<dim3(T_/128, B_*HQ_), 128>>>(Qb, Kb, Vb, attnb);

    // output projection on tensor cores
    {
        int n4 = (M_*HQ_*D_)/4;
        cvt_hilo<<<(n4+255)/256, 256>>>(attnb, ath, atl, n4);
    }
    o_gemm<<<dim3(HID_/128, M_/128), 256, MG_SMEM>>>(ath, atl, owh, owl, out);
}

// round 16
// speedup vs baseline: 1.8756x; 1.8756x over previous
#include <cuda_runtime.h>
#include <cuda_bf16.h>
#include <math.h>
#include <cstdint>

#define HQ_  32
#define HKV_ 8
#define D_   64
#define HID_ 2048
#define B_   2
#define T_   2048
#define M_   (B_*T_)          // 4096 rows (B*T)
#define NQKV_ 3072            // 2048 (Q) + 512 (K) + 512 (V)

typedef unsigned long long ull;

// ---------------- plain-target async copy (sm_80+ base features) -----------
#define CP_ASYNC16(saddr, gptr) \
    asm volatile("cp.async.cg.shared.global [%0], [%1], 16;" \
        :: "r"(saddr), "l"(gptr))
#define CP_COMMIT() asm volatile("cp.async.commit_group;" ::: "memory")
#define CP_WAIT1()  asm volatile("cp.async.wait_group 1;" ::: "memory")
#define CP_WAIT0()  asm volatile("cp.async.wait_group 0;" ::: "memory")

__device__ __forceinline__ uint32_t smem_to_u32(const void* p) {
    uint32_t a;
    asm("{ .reg .u64 t; cvta.to.shared.u64 t, %1; cvt.u32.u64 %0, t; }"
        : "=r"(a) : "l"(p));
    return a;
}

// mma.sync m16n8k16 bf16 -> f32 (plain-target tensor core path)
__device__ __forceinline__ void mma16816(float* c, const uint32_t* a, const uint32_t* b)
{
    asm volatile(
        "mma.sync.aligned.m16n8k16.row.col.f32.bf16.bf16.f32 "
        "{%0,%1,%2,%3}, {%4,%5,%6,%7}, {%8,%9}, {%0,%1,%2,%3};"
        : "+f"(c[0]), "+f"(c[1]), "+f"(c[2]), "+f"(c[3])
        : "r"(a[0]), "r"(a[1]), "r"(a[2]), "r"(a[3]), "r"(b[0]), "r"(b[1]));
}

// single-MUFU exp2 (log2-domain softmax)
__device__ __forceinline__ float ex2(float x) {
    float r;
    asm("ex2.approx.f32 %0, %1;" : "=f"(r) : "f"(x));
    return r;
}
// pack two f32 -> bf16x2 {lo=v0, hi=v1} (RN)
#define PACK_BF16X2(r, v0, v1) \
    asm("cvt.rn.bf16x2.f32 %0, %1, %2;" : "=r"(r) : "f"(v1), "f"(v0))

// ---------------- scratch (device globals; no runtime allocation) ----------
__device__ float g_QKV[(size_t)M_ * NQKV_];
__device__ float g_attn[(size_t)M_ * HQ_ * D_];
// bf16 hi/lo split operands (GEMMs)
__device__ __nv_bfloat16 g_hid_h[(size_t)M_ * HID_],  g_hid_l[(size_t)M_ * HID_];
__device__ __nv_bfloat16 g_w_h[(size_t)NQKV_ * HID_], g_w_l[(size_t)NQKV_ * HID_];
__device__ __nv_bfloat16 g_ow_h[(size_t)HID_ * HQ_ * D_], g_ow_l[(size_t)HID_ * HQ_ * D_];
__device__ __nv_bfloat16 g_at_h[(size_t)M_ * HQ_ * D_],  g_at_l[(size_t)M_ * HQ_ * D_];
// attention operands: Q (log2-scaled, hi/lo), K (hi/lo), V^T (hi/lo)
__device__ __nv_bfloat16 g_Qh[(size_t)B_ * HQ_ * T_ * D_],  g_Ql[(size_t)B_ * HQ_ * T_ * D_];
__device__ __nv_bfloat16 g_Kh[(size_t)B_ * HKV_ * T_ * D_], g_Kl[(size_t)B_ * HKV_ * T_ * D_];
__device__ __nv_bfloat16 g_VTh[(size_t)B_ * HKV_ * D_ * T_], g_VTl[(size_t)B_ * HKV_ * D_ * T_];

// ---------------------------------------------------------------------------
// fp32 -> (bf16 hi, bf16 lo) split conversion, 4 elements/thread.
// ---------------------------------------------------------------------------
__global__ __launch_bounds__(256) void cvt_hilo(
    const float* __restrict__ x, __nv_bfloat16* __restrict__ hi,
    __nv_bfloat16* __restrict__ lo, int n4)
{
    int i = blockIdx.x * blockDim.x + threadIdx.x;
    if (i >= n4) return;
    float4 v = ((const float4*)x)[i];
    __nv_bfloat16 h0 = __float2bfloat16(v.x), h1 = __float2bfloat16(v.y);
    __nv_bfloat16 h2 = __float2bfloat16(v.z), h3 = __float2bfloat16(v.w);
    __nv_bfloat16 l0 = __float2bfloat16(v.x - __bfloat162float(h0));
    __nv_bfloat16 l1 = __float2bfloat16(v.y - __bfloat162float(h1));
    __nv_bfloat16 l2 = __float2bfloat16(v.z - __bfloat162float(h2));
    __nv_bfloat16 l3 = __float2bfloat16(v.w - __bfloat162float(h3));
    ((__nv_bfloat162*)hi)[2*i]   = __nv_bfloat162(h0, h1);
    ((__nv_bfloat162*)hi)[2*i+1] = __nv_bfloat162(h2, h3);
    ((__nv_bfloat162*)lo)[2*i]   = __nv_bfloat162(l0, l1);
    ((__nv_bfloat162*)lo)[2*i+1] = __nv_bfloat162(l2, l3);
}

// ---------------------------------------------------------------------------
// Split-bf16 NT GEMM on mma.sync tensor cores (validated R12, unchanged).
// ---------------------------------------------------------------------------
#define ROWB 80
#define ARRB (128 * ROWB)
#define STAGEB (4 * ARRB)
#define MG_SMEM (2 * STAGEB)

__device__ __forceinline__ void mma_gemm_tile(
    const __nv_bfloat16* __restrict__ Ah, const __nv_bfloat16* __restrict__ Al,
    const __nv_bfloat16* __restrict__ Bh, const __nv_bfloat16* __restrict__ Bl,
    float* __restrict__ C, int K, int ldc, int bm, int bnW, int bnC)
{
    extern __shared__ char dsm[];
    const uint32_t sbase = smem_to_u32(dsm);
    const int tid = threadIdx.x;
    const int wid = tid >> 5, lane = tid & 31;
    const int wm = wid >> 2, wn = wid & 3;
    const int g = lane >> 2, tig = lane & 3;

    const __nv_bfloat16* gsrc[8];
    uint32_t sdst[8];
    #pragma unroll
    for (int i = 0; i < 8; i++) {
        const int id = tid + i * 256;
        const int arr = id >> 9, rem = id & 511;
        const int row = rem >> 2, seg = rem & 3;
        const __nv_bfloat16* base;
        if      (arr == 0) base = Ah + (size_t)(bm  + row) * K;
        else if (arr == 1) base = Al + (size_t)(bm  + row) * K;
        else if (arr == 2) base = Bh + (size_t)(bnW + row) * K;
        else               base = Bl + (size_t)(bnW + row) * K;
        gsrc[i] = base + seg * 8;
        sdst[i] = sbase + arr * ARRB + row * ROWB + seg * 16;
    }

    float acc[4][4][4];
    #pragma unroll
    for (int mt = 0; mt < 4; mt++)
        #pragma unroll
        for (int nt = 0; nt < 4; nt++)
            #pragma unroll
            for (int r = 0; r < 4; r++) acc[mt][nt][r] = 0.f;

    const int S = K >> 5;
    #pragma unroll
    for (int i = 0; i < 8; i++) CP_ASYNC16(sdst[i], gsrc[i]);
    CP_COMMIT();

    for (int s = 0; s < S; s++) {
        if (s + 1 < S) {
            const uint32_t boff = ((s + 1) & 1) * STAGEB;
            const int k0 = (s + 1) << 5;
            #pragma unroll
            for (int i = 0; i < 8; i++) CP_ASYNC16(sdst[i] + boff, gsrc[i] + k0);
            CP_COMMIT();
            CP_WAIT1();
        } else {
            CP_WAIT0();
        }
        __syncthreads();

        const char* sb = dsm + (s & 1) * STAGEB;
        const char* AHs = sb;
        const char* ALs = sb + ARRB;
        const char* BHs = sb + 2 * ARRB;
        const char* BLs = sb + 3 * ARRB;

        #pragma unroll
        for (int kk = 0; kk < 2; kk++) {
            const int wb = kk * 8;
            uint32_t ah[4][4], al[4][4], bh[4][2], bl[4][2];
            #pragma unroll
            for (int mt = 0; mt < 4; mt++) {
                const int r0 = wm * 64 + mt * 16 + g;
                const uint32_t o00 = r0 * ROWB + (wb + tig) * 4;
                const uint32_t o10 = (r0 + 8) * ROWB + (wb + tig) * 4;
                ah[mt][0] = *(const uint32_t*)(AHs + o00);
                ah[mt][1] = *(const uint32_t*)(AHs + o10);
                ah[mt][2] = *(const uint32_t*)(AHs + o00 + 16);
                ah[mt][3] = *(const uint32_t*)(AHs + o10 + 16);
                al[mt][0] = *(const uint32_t*)(ALs + o00);
                al[mt][1] = *(const uint32_t*)(ALs + o10);
                al[mt][2] = *(const uint32_t*)(ALs + o00 + 16);
                al[mt][3] = *(const uint32_t*)(ALs + o10 + 16);
            }
            #pragma unroll
            for (int nt = 0; nt < 4; nt++) {
                const int n = wn * 32 + nt * 8 + g;
                const uint32_t o = n * ROWB + (wb + tig) * 4;
                bh[nt][0] = *(const uint32_t*)(BHs + o);
                bh[nt][1] = *(const uint32_t*)(BHs + o + 16);
                bl[nt][0] = *(const uint32_t*)(BLs + o);
                bl[nt][1] = *(const uint32_t*)(BLs + o + 16);
            }
            #pragma unroll
            for (int mt = 0; mt < 4; mt++)
                #pragma unroll
                for (int nt = 0; nt < 4; nt++) {
                    mma16816(acc[mt][nt], ah[mt], bh[nt]);
                    mma16816(acc[mt][nt], ah[mt], bl[nt]);
                    mma16816(acc[mt][nt], al[mt], bh[nt]);
                }
        }
        __syncthreads();
    }

    #pragma unroll
    for (int mt = 0; mt < 4; mt++) {
        const int r0 = bm + wm * 64 + mt * 16 + g;
        #pragma unroll
        for (int nt = 0; nt < 4; nt++) {
            float* cp = C + (size_t)r0 * ldc + bnC + wn * 32 + nt * 8 + tig * 2;
            *(float2*)cp = make_float2(acc[mt][nt][0], acc[mt][nt][1]);
            *(float2*)(cp + (size_t)8 * ldc) = make_float2(acc[mt][nt][2], acc[mt][nt][3]);
        }
    }
}

__global__ __launch_bounds__(256) void qkv_gemm(
    const __nv_bfloat16* __restrict__ hidh, const __nv_bfloat16* __restrict__ hidl,
    const __nv_bfloat16* __restrict__ wh,   const __nv_bfloat16* __restrict__ wl,
    float* __restrict__ C)
{
    const int bn = blockIdx.x * 128;
    mma_gemm_tile(hidh, hidl, wh, wl, C, HID_, NQKV_, blockIdx.y * 128, bn, bn);
}

__global__ __launch_bounds__(256) void o_gemm(
    const __nv_bfloat16* __restrict__ ah, const __nv_bfloat16* __restrict__ al,
    const __nv_bfloat16* __restrict__ wh, const __nv_bfloat16* __restrict__ wl,
    float* __restrict__ C)
{
    mma_gemm_tile(ah, al, wh, wl, C, HQ_ * D_, HID_,
                  blockIdx.y * 128, blockIdx.x * 128, blockIdx.x * 128);
}

// ---------------------------------------------------------------------------
// Bias + RoPE + split-bf16 + relayout.
// Q -> (B,HQ,T,D) bf16 hi/lo with 0.125*log2(e) folded (log2-domain scores).
// K -> (B,HKV,T,D) bf16 hi/lo.  V -> TRANSPOSED (B,HKV,D,T) bf16 hi/lo.
// ---------------------------------------------------------------------------
__global__ __launch_bounds__(128) void rope_reshape(
    const float* __restrict__ qkv,
    const float* __restrict__ qb, const float* __restrict__ kb,
    const float* __restrict__ vb,
    __nv_bfloat16* __restrict__ Qh, __nv_bfloat16* __restrict__ Ql,
    __nv_bfloat16* __restrict__ Kh, __nv_bfloat16* __restrict__ Kl,
    __nv_bfloat16* __restrict__ VTh, __nv_bfloat16* __restrict__ VTl)
{
    const int bt = blockIdx.x;
    const int b = bt / T_, t = bt % T_;
    const float* row = qkv + (size_t)bt * NQKV_;
    const float pos = (float)t;
    const float LOG_TH_OVER_HALF = 9.210340371976184f / 32.0f;
    const float QSCALE = 0.125f * 1.4426950408889634f;

    for (int it = threadIdx.x; it < HQ_*32; it += blockDim.x) {
        int h = it >> 5, j = it & 31;
        float invf = expf(-(float)j * LOG_TH_OVER_HALF);
        float sn, cs; sincosf(pos * invf, &sn, &cs);
        float x1 = row[h*64 + j]      + qb[h*64 + j];
        float x2 = row[h*64 + j + 32] + qb[h*64 + j + 32];
        float r1 = (x1*cs - x2*sn) * QSCALE;
        float r2 = (x2*cs + x1*sn) * QSCALE;
        size_t o = (((size_t)b*HQ_ + h)*T_ + t)*64;
        __nv_bfloat16 h1 = __float2bfloat16(r1), h2 = __float2bfloat16(r2);
        Qh[o + j]      = h1; Ql[o + j]      = __float2bfloat16(r1 - __bfloat162float(h1));
        Qh[o + j + 32] = h2; Ql[o + j + 32] = __float2bfloat16(r2 - __bfloat162float(h2));
    }
    for (int it = threadIdx.x; it < HKV_*32; it += blockDim.x) {
        int h = it >> 5, j = it & 31;
        float invf = expf(-(float)j * LOG_TH_OVER_HALF);
        float sn, cs; sincosf(pos * invf, &sn, &cs);
        float x1 = row[2048 + h*64 + j]      + kb[h*64 + j];
        float x2 = row[2048 + h*64 + j + 32] + kb[h*64 + j + 32];
        float r1 = x1*cs - x2*sn;
        float r2 = x2*cs + x1*sn;
        size_t o = (((size_t)b*HKV_ + h)*T_ + t)*64;
        __nv_bfloat16 h1 = __float2bfloat16(r1), h2 = __float2bfloat16(r2);
        Kh[o + j]      = h1; Kl[o + j]      = __float2bfloat16(r1 - __bfloat162float(h1));
        Kh[o + j + 32] = h2; Kl[o + j + 32] = __float2bfloat16(r2 - __bfloat162float(h2));
    }
    for (int it = threadIdx.x; it < HKV_*64; it += blockDim.x) {
        int h = it >> 6, d = it & 63;
        float v = row[2560 + it] + vb[it];
        size_t o = (((size_t)b*HKV_ + h)*64 + d)*T_ + t;   // transposed (d, t)
        __nv_bfloat16 hv = __float2bfloat16(v);
        VTh[o] = hv; VTl[o] = __float2bfloat16(v - __bfloat162float(hv));
    }
}

// ---------------------------------------------------------------------------
// Tensor-core causal GQA flash attention.
// Grid (T/64, B*HQ), 128 threads (4 warps, 16 q-rows each). KV tiles of 64
// keys stream via cp.async double-buffer (K hi/lo row-major (key,d) + V^T
// hi/lo (d,key)). Scores: 3-way split-bf16 mma. Softmax exact fp32 in log2
// domain (single-MUFU ex2). P split hi/lo -> PV via 3-way mma.
// ---------------------------------------------------------------------------
#define AROWB 144                     // 64 bf16 = 128B, padded to 144B
#define ATILEB (64 * AROWB)           // 9216 B
#define ASTAGE (4 * ATILEB)           // 36864 B
#define AT_SMEM (2 * ASTAGE)          // 73728 B

__global__ __launch_bounds__(128) void attn_mma(
    const __nv_bfloat16* __restrict__ Qh, const __nv_bfloat16* __restrict__ Ql,
    const __nv_bfloat16* __restrict__ Kh, const __nv_bfloat16* __restrict__ Kl,
    const __nv_bfloat16* __restrict__ VTh, const __nv_bfloat16* __restrict__ VTl,
    float* __restrict__ O)
{
    extern __shared__ char dsm[];
    const uint32_t sbase = smem_to_u32(dsm);
    const int qt = (gridDim.x - 1) - blockIdx.x;   // longest first
    const int bh = blockIdx.y;
    const int b = bh / HQ_, h = bh % HQ_;
    const int kvh = h / (HQ_ / HKV_);
    const int tid = threadIdx.x;
    const int w = tid >> 5, lane = tid & 31;
    const int g = lane >> 2, tig = lane & 3;
    const int qrow0 = qt * 64 + w * 16;            // warp's first q row

    const __nv_bfloat16* Qph  = Qh  + (((size_t)b*HQ_  + h  )*T_) * 64;
    const __nv_bfloat16* Qpl  = Ql  + (((size_t)b*HQ_  + h  )*T_) * 64;
    const __nv_bfloat16* Kph  = Kh  + (((size_t)b*HKV_ + kvh)*T_) * 64;
    const __nv_bfloat16* Kpl  = Kl  + (((size_t)b*HKV_ + kvh)*T_) * 64;
    const __nv_bfloat16* VTph = VTh + (((size_t)b*HKV_ + kvh)*64) * T_;
    const __nv_bfloat16* VTpl = VTl + (((size_t)b*HKV_ + kvh)*64) * T_;

    // Q fragments (A layout, validated): [kc][0]=row g, [1]=row g+8, [2]=k+8, [3]=both
    uint32_t qfh[4][4], qfl[4][4];
    #pragma unroll
    for (int kc = 0; kc < 4; kc++) {
        const size_t r0 = (size_t)(qrow0 + g) * 64 + kc*16 + 2*tig;
        const size_t r1 = (size_t)(qrow0 + g + 8) * 64 + kc*16 + 2*tig;
        qfh[kc][0] = *(const uint32_t*)(Qph + r0);
        qfh[kc][1] = *(const uint32_t*)(Qph + r1);
        qfh[kc][2] = *(const uint32_t*)(Qph + r0 + 8);
        qfh[kc][3] = *(const uint32_t*)(Qph + r1 + 8);
        qfl[kc][0] = *(const uint32_t*)(Qpl + r0);
        qfl[kc][1] = *(const uint32_t*)(Qpl + r1);
        qfl[kc][2] = *(const uint32_t*)(Qpl + r0 + 8);
        qfl[kc][3] = *(const uint32_t*)(Qpl + r1 + 8);
    }

    // cp.async descriptors: per thread, fixed c = tid&7, rows tid>>3 + 16*s
    const int crow = tid >> 3, cseg = tid & 7;
    const __nv_bfloat16* gK0 = Kph  + (size_t)crow * 64 + cseg * 8;
    const __nv_bfloat16* gK1 = Kpl  + (size_t)crow * 64 + cseg * 8;
    const __nv_bfloat16* gV0 = VTph + (size_t)crow * T_ + cseg * 8;
    const __nv_bfloat16* gV1 = VTpl + (size_t)crow * T_ + cseg * 8;
    const uint32_t sd = sbase + crow * AROWB + cseg * 16;

    float m0 = -1e30f, m1 = -1e30f, l0 = 0.f, l1 = 0.f;
    float acc[8][4];
    #pragma unroll
    for (int dc = 0; dc < 8; dc++)
        #pragma unroll
        for (int r = 0; r < 4; r++) acc[dc][r] = 0.f;

    const int nkt = qt + 1;
    // prologue: stage 0 -> buffer 0
    #pragma unroll
    for (int s = 0; s < 4; s++) {
        CP_ASYNC16(sd + s*2304,                gK0 + (size_t)s*16*64);
        CP_ASYNC16(sd + s*2304 +   ATILEB,     gK1 + (size_t)s*16*64);
        CP_ASYNC16(sd + s*2304 + 2*ATILEB,     gV0 + (size_t)s*16*T_);
        CP_ASYNC16(sd + s*2304 + 3*ATILEB,     gV1 + (size_t)s*16*T_);
    }
    CP_COMMIT();

    for (int kt = 0; kt < nkt; kt++) {
        if (kt + 1 < nkt) {
            const uint32_t bo = ((kt + 1) & 1) * ASTAGE;
            const size_t koff = (size_t)(kt + 1) * 64 * 64;   // K arrays advance 64 rows
            const size_t voff = (size_t)(kt + 1) * 64;        // VT arrays advance 64 cols
            #pragma unroll
            for (int s = 0; s < 4; s++) {
                CP_ASYNC16(sd + bo + s*2304,            gK0 + koff + (size_t)s*16*64);
                CP_ASYNC16(sd + bo + s*2304 +   ATILEB, gK1 + koff + (size_t)s*16*64);
                CP_ASYNC16(sd + bo + s*2304 + 2*ATILEB, gV0 + voff + (size_t)s*16*T_);
                CP_ASYNC16(sd + bo + s*2304 + 3*ATILEB, gV1 + voff + (size_t)s*16*T_);
            }
            CP_COMMIT();
            CP_WAIT1();
        } else {
            CP_WAIT0();
        }
        __syncthreads();

        const char* sb  = dsm + (kt & 1) * ASTAGE;
        const char* KHs = sb;
        const char* KLs = sb + ATILEB;
        const char* VHs = sb + 2*ATILEB;
        const char* VLs = sb + 3*ATILEB;

        // ---- scores: s[nc] = m16n8 over keys nc*8..+8, k = d (3-way split)
        float s[8][4];
        #pragma unroll
        for (int nc = 0; nc < 8; nc++)
            #pragma unroll
            for (int r = 0; r < 4; r++) s[nc][r] = 0.f;
        #pragma unroll
        for (int nc = 0; nc < 8; nc++) {
            const uint32_t o = (nc*8 + g) * AROWB;
            #pragma unroll
            for (int kc = 0; kc < 4; kc++) {
                const uint32_t ko = o + (kc*16 + 2*tig) * 2;
                uint32_t bhf[2], blf[2];
                bhf[0] = *(const uint32_t*)(KHs + ko);
                bhf[1] = *(const uint32_t*)(KHs + ko + 16);
                blf[0] = *(const uint32_t*)(KLs + ko);
                blf[1] = *(const uint32_t*)(KLs + ko + 16);
                mma16816(s[nc], qfh[kc], bhf);
                mma16816(s[nc], qfh[kc], blf);
                mma16816(s[nc], qfl[kc], bhf);
            }
        }
        // ---- causal mask (only diagonal tile: q block == kv block size)
        if (kt == qt) {
            const int lr0 = w*16 + g, lr1 = lr0 + 8;
            #pragma unroll
            for (int nc = 0; nc < 8; nc++) {
                const int c0 = nc*8 + 2*tig, c1 = c0 + 1;
                if (c0 > lr0) s[nc][0] = -1e30f;
                if (c1 > lr0) s[nc][1] = -1e30f;
                if (c0 > lr1) s[nc][2] = -1e30f;
                if (c1 > lr1) s[nc][3] = -1e30f;
            }
        }
        // ---- row max (quad shfl reduce)
        float t0 = s[0][0], t1 = s[0][2];
        #pragma unroll
        for (int nc = 0; nc < 8; nc++) {
            t0 = fmaxf(t0, fmaxf(s[nc][0], s[nc][1]));
            t1 = fmaxf(t1, fmaxf(s[nc][2], s[nc][3]));
        }
        t0 = fmaxf(t0, __shfl_xor_sync(0xffffffff, t0, 1));
        t0 = fmaxf(t0, __shfl_xor_sync(0xffffffff, t0, 2));
        t1 = fmaxf(t1, __shfl_xor_sync(0xffffffff, t1, 1));
        t1 = fmaxf(t1, __shfl_xor_sync(0xffffffff, t1, 2));
        const float mn0 = fmaxf(m0, t0), mn1 = fmaxf(m1, t1);
        const float sc0 = ex2(m0 - mn0), sc1 = ex2(m1 - mn1);
        // ---- p = ex2(s - m), row sums
        float ps0 = 0.f, ps1 = 0.f;
        #pragma unroll
        for (int nc = 0; nc < 8; nc++) {
            s[nc][0] = ex2(s[nc][0] - mn0); ps0 += s[nc][0];
            s[nc][1] = ex2(s[nc][1] - mn0); ps0 += s[nc][1];
            s[nc][2] = ex2(s[nc][2] - mn1); ps1 += s[nc][2];
            s[nc][3] = ex2(s[nc][3] - mn1); ps1 += s[nc][3];
        }
        ps0 += __shfl_xor_sync(0xffffffff, ps0, 1);
        ps0 += __shfl_xor_sync(0xffffffff, ps0, 2);
        ps1 += __shfl_xor_sync(0xffffffff, ps1, 1);
        ps1 += __shfl_xor_sync(0xffffffff, ps1, 2);
        l0 = l0*sc0 + ps0; l1 = l1*sc1 + ps1;
        m0 = mn0; m1 = mn1;
        // ---- pack P hi/lo into A fragments (C->A identity layout)
        uint32_t pfh[4][4], pfl[4][4];
        #pragma unroll
        for (int jc = 0; jc < 4; jc++) {
            const float* a = s[2*jc];
            const float* c = s[2*jc + 1];
            PACK_BF16X2(pfh[jc][0], a[0], a[1]);
            PACK_BF16X2(pfh[jc][1], a[2], a[3]);
            PACK_BF16X2(pfh[jc][2], c[0], c[1]);
            PACK_BF16X2(pfh[jc][3], c[2], c[3]);
            // residuals
            float r[8];
            r[0] = a[0] - __uint_as_float(pfh[jc][0] << 16);
            r[1] = a[1] - __uint_as_float(pfh[jc][0] & 0xFFFF0000u);
            r[2] = a[2] - __uint_as_float(pfh[jc][1] << 16);
            r[3] = a[3] - __uint_as_float(pfh[jc][1] & 0xFFFF0000u);
            r[4] = c[0] - __uint_as_float(pfh[jc][2] << 16);
            r[5] = c[1] - __uint_as_float(pfh[jc][2] & 0xFFFF0000u);
            r[6] = c[2] - __uint_as_float(pfh[jc][3] << 16);
            r[7] = c[3] - __uint_as_float(pfh[jc][3] & 0xFFFF0000u);
            PACK_BF16X2(pfl[jc][0], r[0], r[1]);
            PACK_BF16X2(pfl[jc][1], r[2], r[3]);
            PACK_BF16X2(pfl[jc][2], r[4], r[5]);
            PACK_BF16X2(pfl[jc][3], r[6], r[7]);
        }
        // ---- rescale acc, then PV (3-way split)
        #pragma unroll
        for (int dc = 0; dc < 8; dc++) {
            acc[dc][0] *= sc0; acc[dc][1] *= sc0;
            acc[dc][2] *= sc1; acc[dc][3] *= sc1;
        }
        #pragma unroll
        for (int dc = 0; dc < 8; dc++) {
            const uint32_t o = (dc*8 + g) * AROWB;
            #pragma unroll
            for (int jc = 0; jc < 4; jc++) {
                const uint32_t jo = o + (jc*16 + 2*tig) * 2;
                uint32_t vhf[2], vlf[2];
                vhf[0] = *(const uint32_t*)(VHs + jo);
                vhf[1] = *(const uint32_t*)(VHs + jo + 16);
                vlf[0] = *(const uint32_t*)(VLs + jo);
                vlf[1] = *(const uint32_t*)(VLs + jo + 16);
                mma16816(acc[dc], pfh[jc], vhf);
                mma16816(acc[dc], pfh[jc], vlf);
                mma16816(acc[dc], pfl[jc], vhf);
            }
        }
        __syncthreads();
    }

    // epilogue -> O (B, T, HQ*D)
    const float i0 = 1.0f / l0, i1 = 1.0f / l1;
    const int r0 = qrow0 + g, r1 = r0 + 8;
    float* O0 = O + ((size_t)(b*T_ + r0)*HQ_ + h) * 64;
    float* O1 = O + ((size_t)(b*T_ + r1)*HQ_ + h) * 64;
    #pragma unroll
    for (int dc = 0; dc < 8; dc++) {
        const int c = dc*8 + 2*tig;
        *(float2*)(O0 + c) = make_float2(acc[dc][0]*i0, acc[dc][1]*i0);
        *(float2*)(O1 + c) = make_float2(acc[dc][2]*i1, acc[dc][3]*i1);
    }
}

// ---------------------------------------------------------------------------
extern "C" void kernel_launch(void* const* d_in, const int* in_sizes, int n_in,
                              void* d_out, int out_size)
{
    (void)in_sizes; (void)n_in; (void)out_size;
    const float* hidden = (const float*)d_in[0];
    const float* q_w = (const float*)d_in[3];
    const float* q_b = (const float*)d_in[4];
    const float* k_w = (const float*)d_in[5];
    const float* k_b = (const float*)d_in[6];
    const float* v_w = (const float*)d_in[7];
    const float* v_b = (const float*)d_in[8];
    const float* o_w = (const float*)d_in[9];
    float* out = (float*)d_out;

    float *qkv, *attnb;
    cudaGetSymbolAddress((void**)&qkv,   g_QKV);
    cudaGetSymbolAddress((void**)&attnb, g_attn);
    __nv_bfloat16 *hidh, *hidl, *wh, *wl, *owh, *owl, *ath, *atl;
    __nv_bfloat16 *Qh, *Ql, *Kh, *Kl, *VTh, *VTl;
    cudaGetSymbolAddress((void**)&hidh, g_hid_h);
    cudaGetSymbolAddress((void**)&hidl, g_hid_l);
    cudaGetSymbolAddress((void**)&wh,   g_w_h);
    cudaGetSymbolAddress((void**)&wl,   g_w_l);
    cudaGetSymbolAddress((void**)&owh,  g_ow_h);
    cudaGetSymbolAddress((void**)&owl,  g_ow_l);
    cudaGetSymbolAddress((void**)&ath,  g_at_h);
    cudaGetSymbolAddress((void**)&atl,  g_at_l);
    cudaGetSymbolAddress((void**)&Qh,   g_Qh);
    cudaGetSymbolAddress((void**)&Ql,   g_Ql);
    cudaGetSymbolAddress((void**)&Kh,   g_Kh);
    cudaGetSymbolAddress((void**)&Kl,   g_Kl);
    cudaGetSymbolAddress((void**)&VTh,  g_VTh);
    cudaGetSymbolAddress((void**)&VTl,  g_VTl);

    cudaFuncSetAttribute(qkv_gemm, cudaFuncAttributeMaxDynamicSharedMemorySize, MG_SMEM);
    cudaFuncSetAttribute(o_gemm,   cudaFuncAttributeMaxDynamicSharedMemorySize, MG_SMEM);
    cudaFuncSetAttribute(attn_mma, cudaFuncAttributeMaxDynamicSharedMemorySize, AT_SMEM);

    // hi/lo split conversions
    {
        int n4;
        n4 = (M_*HID_)/4;       cvt_hilo<<<(n4+255)/256, 256>>>(hidden, hidh, hidl, n4);
        n4 = (2048*HID_)/4;     cvt_hilo<<<(n4+255)/256, 256>>>(q_w, wh, wl, n4);
        n4 = (512*HID_)/4;      cvt_hilo<<<(n4+255)/256, 256>>>(k_w, wh + (size_t)2048*HID_, wl + (size_t)2048*HID_, n4);
        n4 = (512*HID_)/4;      cvt_hilo<<<(n4+255)/256, 256>>>(v_w, wh + (size_t)2560*HID_, wl + (size_t)2560*HID_, n4);
        n4 = (HID_*HQ_*D_)/4;   cvt_hilo<<<(n4+255)/256, 256>>>(o_w, owh, owl, n4);
    }

    // QKV projection on tensor cores (bias deferred to rope_reshape)
    qkv_gemm<<<dim3(NQKV_/128, M_/128), 256, MG_SMEM>>>(hidh, hidl, wh, wl, qkv);

    // bias + RoPE + bf16 split + relayout (V transposed)
    rope_reshape<<<M_, 128>>>(qkv, q_b, k_b, v_b, Qh, Ql, Kh, Kl, VTh, VTl);

    // tensor-core causal GQA attention
    attn_mma<<<dim3(T_/64, B_*HQ_), 128, AT_SMEM>>>(Qh, Ql, Kh, Kl, VTh, VTl, attnb);

    // output projection on tensor cores
    {
        int n4 = (M_*HQ_*D_)/4;
        cvt_hilo<<<(n4+255)/256, 256>>>(attnb, ath, atl, n4);
    }
    o_gemm<<<dim3(HID_/128, M_/128), 256, MG_SMEM>>>(ath, atl, owh, owl, out);
}